// round 6
// baseline (speedup 1.0000x reference)
#include <cuda_runtime.h>
#include <cuda_fp16.h>
#include <cstdint>
#include <math.h>

// ---------------- constants ----------------
#define Dd      16
#define CTXd    128
#define SAMP    64
#define THREADS 512
#define STRB    400           // bytes per row: 192 fp16 (384B) + 16B pad -> conflict-free
#define WIMG    76800         // 192 rows * 400 B
#define W3IMG   6400          // 16 rows * 400 B

// smem layout (bytes)
#define SM_W1   0
#define SM_W2   76800
#define SM_W3   153600
#define SM_A    160000        // activation: 128 rows x 400 B (51200)
#define SM_BIAS 211200        // 384 fp32 (1536)
#define SM_TOT  212736
// sRed (32KB) aliases SM_W1 region (dead after layer 1)

// ---------------- weight images (fp16, stride-400 rows) ----------------
__device__ __align__(16) uint8_t g_w1i[WIMG];
__device__ __align__(16) uint8_t g_w2i[WIMG];
__device__ __align__(16) uint8_t g_w3i[W3IMG];
__device__ float g_b1p[192];

__global__ void prep(const float* __restrict__ W1, const float* __restrict__ W2,
                     const float* __restrict__ W3, const float* __restrict__ b1,
                     const float* __restrict__ t)
{
    int idx = blockIdx.x * blockDim.x + threadIdx.x;
    if (idx < 27648) {                       // W1: k<144, n<192
        int k = idx / 192, n = idx - k * 192;
        *(__half*)(g_w1i + n * STRB + k * 2) = __float2half_rn(W1[(size_t)k * 192 + n]);
    } else if (idx < 64512) {                // W2: 192x192
        int i = idx - 27648;
        int k = i / 192, n = i - k * 192;
        *(__half*)(g_w2i + n * STRB + k * 2) = __float2half_rn(W2[(size_t)k * 192 + n]);
    } else if (idx < 67584) {                // W3: 192x16
        int i = idx - 64512;
        int k = i / 16, n = i - k * 16;
        *(__half*)(g_w3i + n * STRB + k * 2) = __float2half_rn(W3[(size_t)k * 16 + n]);
    } else if (idx < 67776) {                // b1' = b1 + t*W1[144,:]
        int n = idx - 67584;
        g_b1p[n] = b1[n] + t[0] * W1[144 * 192 + n];
    }
}

// ---------------- PTX helpers ----------------
__device__ __forceinline__ uint32_t smem_u32(const void* p) {
    uint32_t a;
    asm("{ .reg .u64 t; cvta.to.shared.u64 t, %1; cvt.u32.u64 %0, t; }" : "=r"(a) : "l"(p));
    return a;
}
__device__ __forceinline__ void cpa16(uint32_t dst, const void* src) {
    asm volatile("cp.async.cg.shared.global [%0], [%1], 16;" :: "r"(dst), "l"(src) : "memory");
}
__device__ __forceinline__ void cpa_commit() {
    asm volatile("cp.async.commit_group;" ::: "memory");
}
template<int N>
__device__ __forceinline__ void cpa_wait() {
    asm volatile("cp.async.wait_group %0;" :: "n"(N) : "memory");
}
__device__ __forceinline__ void ldsm4(uint32_t (&r)[4], uint32_t addr) {
    asm volatile("ldmatrix.sync.aligned.m8n8.x4.shared.b16 {%0,%1,%2,%3}, [%4];"
                 : "=r"(r[0]), "=r"(r[1]), "=r"(r[2]), "=r"(r[3]) : "r"(addr));
}
__device__ __forceinline__ void mma16816(float (&d)[4], const uint32_t (&a)[4],
                                         uint32_t b0, uint32_t b1)
{
    asm volatile("mma.sync.aligned.m16n8k16.row.col.f32.f16.f16.f32 "
                 "{%0,%1,%2,%3}, {%4,%5,%6,%7}, {%8,%9}, {%0,%1,%2,%3};"
                 : "+f"(d[0]), "+f"(d[1]), "+f"(d[2]), "+f"(d[3])
                 : "r"(a[0]), "r"(a[1]), "r"(a[2]), "r"(a[3]), "r"(b0), "r"(b1));
}

// linear (stride-400) ldmatrix addresses — conflict-free by construction
__device__ __forceinline__ uint32_t aAddr(uint32_t base, int m0, int kt, int lane) {
    int row = m0 + (lane & 7) + ((lane >> 3) & 1) * 8;
    return base + row * STRB + kt * 32 + ((lane >> 4) & 1) * 16;
}
__device__ __forceinline__ uint32_t bAddr(uint32_t base, int n0, int kt, int lane) {
    int row = n0 + (lane & 7) + ((lane >> 4) & 1) * 8;
    return base + row * STRB + kt * 32 + ((lane >> 3) & 1) * 16;
}
__device__ __forceinline__ void stH2(char* sm, int off, int row, int c0, float v0, float v1) {
    *(__half2*)(sm + off + row * STRB + c0 * 2) = __floats2half2_rn(v0, v1);
}

__device__ __forceinline__ void gelu2(float a0, float a1, float& g0, float& g1,
                                      float& p0, float& p1)
{
    float c0 = 0.5f * (1.0f + erff(a0 * 0.70710678118654752f));
    float c1 = 0.5f * (1.0f + erff(a1 * 0.70710678118654752f));
    float q0 = 0.3989422804014327f * __expf(-0.5f * a0 * a0);
    float q1 = 0.3989422804014327f * __expf(-0.5f * a1 * a1);
    g0 = a0 * c0;  g1 = a1 * c1;
    p0 = c0 + a0 * q0;  p1 = c1 + a1 * q1;
}

// bias + gelu on primal frag, gelu'(a)*u on tangent frag, both -> smem A
__device__ __forceinline__ void epilogue(float (&accP)[6][4], float (&accT)[6][4],
                                         const float* bias, char* smem,
                                         int mh, int n0, int lane)
{
    const int r0 = mh * 16 + (lane >> 2);
    const int cl = 2 * (lane & 3);
#pragma unroll
    for (int nt = 0; nt < 6; nt++) {
        const int c0 = n0 + 8 * nt + cl;
        const float bb0 = bias[c0], bb1 = bias[c0 + 1];
#pragma unroll
        for (int rh = 0; rh < 2; rh++) {
            const int s = r0 + 8 * rh;
            float a0 = accP[nt][2 * rh]     + bb0;
            float a1 = accP[nt][2 * rh + 1] + bb1;
            float g0, g1, p0, p1;
            gelu2(a0, a1, g0, g1, p0, p1);
            stH2(smem, SM_A, s, c0, g0, g1);
            stH2(smem, SM_A, 64 + s, c0, accT[nt][2 * rh] * p0, accT[nt][2 * rh + 1] * p1);
        }
    }
}

// ---------------- main kernel ----------------
__global__ void __launch_bounds__(THREADS, 1)
odefunc_mma4(const float* __restrict__ y,
             const float* __restrict__ h,
             const float* __restrict__ eps,
             const float* __restrict__ b2,
             const float* __restrict__ b3,
             float* __restrict__ out, int Bsz)
{
    extern __shared__ __align__(16) char smem[];
    const uint32_t sbase = smem_u32(smem);
    const uint32_t swW1 = sbase + SM_W1;
    const uint32_t swW2 = sbase + SM_W2;
    const uint32_t swW3 = sbase + SM_W3;
    const uint32_t swA  = sbase + SM_A;
    float* sBias = (float*)(smem + SM_BIAS);
    float* sRed  = (float*)(smem + SM_W1);     // aliases W1 (dead after layer 1)

    const int tid  = threadIdx.x;
    const int lane = tid & 31;
    const int w    = tid >> 5;          // 0..15
    const int nq   = w & 3;             // n-quarter (48 cols)
    const int mh   = w >> 2;            // m-group (16 rows) 0..3
    const int n0   = nq * 48;

    const int row0 = blockIdx.x * SAMP;
    float* outF    = out;
    float* outLogp = out + (size_t)Bsz * Dd;
    float* outDh   = out + (size_t)Bsz * (Dd + 1);

    // ---- prologue: issue ALL weight copies up front ----
    for (int i = tid; i < WIMG / 16; i += THREADS) cpa16(swW1 + i * 16, g_w1i + i * 16);
    cpa_commit();
    for (int i = tid; i < WIMG / 16; i += THREADS) cpa16(swW2 + i * 16, g_w2i + i * 16);
    cpa_commit();
    for (int i = tid; i < W3IMG / 16; i += THREADS) cpa16(swW3 + i * 16, g_w3i + i * 16);
    cpa_commit();

    // biases, zero dh, stage inputs (overlap the copies)
    if (tid < 192) sBias[tid] = g_b1p[tid];
    else if (tid >= 256 && tid < 448) sBias[tid - 64] = __ldg(b2 + (tid - 256));
    {
        float4* dhp = (float4*)(outDh + (size_t)row0 * CTXd);
        const float4 z4 = make_float4(0.f, 0.f, 0.f, 0.f);
        for (int i = tid; i < SAMP * CTXd / 4; i += THREADS) dhp[i] = z4;
    }
    {   // primal rows 0..63: [y(16) | h(128)] = K 144
        const int s = tid >> 3, kb = tid & 7;
#pragma unroll
        for (int j = 0; j < 9; j++) {
            const int k = 2 * (kb + 8 * j);
            float2 v;
            if (k < 16) v = *(const float2*)(y + (size_t)(row0 + s) * Dd + k);
            else        v = *(const float2*)(h + (size_t)(row0 + s) * CTXd + (k - 16));
            stH2(smem, SM_A, s, k, v.x, v.y);
        }
        // tangent rows 64..127: eps in k 0..15
        const int k = 2 * (tid & 7);
        float2 v = *(const float2*)(eps + (size_t)(row0 + s) * Dd + k);
        stH2(smem, SM_A, 64 + s, k, v.x, v.y);
    }
    cpa_wait<2>();                    // W1 resident
    __syncthreads();

    // ---------------- layer 1 ----------------
    float accP[6][4], accT[6][4];
#pragma unroll
    for (int j = 0; j < 6; j++)
#pragma unroll
        for (int q = 0; q < 4; q++) { accP[j][q] = 0.f; accT[j][q] = 0.f; }

    {   // kt = 0: shared B for primal + tangent (eps lives only in k<16)
        uint32_t b[3][4], aP[4], aT[4];
#pragma unroll
        for (int np = 0; np < 3; np++) ldsm4(b[np], bAddr(swW1, n0 + 16 * np, 0, lane));
        ldsm4(aP, aAddr(swA, mh * 16,      0, lane));
        ldsm4(aT, aAddr(swA, 64 + mh * 16, 0, lane));
#pragma unroll
        for (int np = 0; np < 3; np++) {
            mma16816(accP[2 * np],     aP, b[np][0], b[np][1]);
            mma16816(accP[2 * np + 1], aP, b[np][2], b[np][3]);
            mma16816(accT[2 * np],     aT, b[np][0], b[np][1]);
            mma16816(accT[2 * np + 1], aT, b[np][2], b[np][3]);
        }
    }
#pragma unroll
    for (int kt = 1; kt < 9; kt++) {
        uint32_t b[3][4], aP[4];
#pragma unroll
        for (int np = 0; np < 3; np++) ldsm4(b[np], bAddr(swW1, n0 + 16 * np, kt, lane));
        ldsm4(aP, aAddr(swA, mh * 16, kt, lane));
#pragma unroll
        for (int np = 0; np < 3; np++) {
            mma16816(accP[2 * np],     aP, b[np][0], b[np][1]);
            mma16816(accP[2 * np + 1], aP, b[np][2], b[np][3]);
        }
    }
    __syncthreads();                  // layer-1 act reads done

    epilogue(accP, accT, sBias, smem, mh, n0, lane);
    cpa_wait<0>();                    // W2 + W3 resident
    __syncthreads();

    // ---------------- layer 2 ----------------
#pragma unroll
    for (int j = 0; j < 6; j++)
#pragma unroll
        for (int q = 0; q < 4; q++) { accP[j][q] = 0.f; accT[j][q] = 0.f; }
#pragma unroll
    for (int kt = 0; kt < 12; kt++) {
        uint32_t b[3][4], aP[4], aT[4];
#pragma unroll
        for (int np = 0; np < 3; np++) ldsm4(b[np], bAddr(swW2, n0 + 16 * np, kt, lane));
        ldsm4(aP, aAddr(swA, mh * 16,      kt, lane));
        ldsm4(aT, aAddr(swA, 64 + mh * 16, kt, lane));
#pragma unroll
        for (int np = 0; np < 3; np++) {
            mma16816(accP[2 * np],     aP, b[np][0], b[np][1]);
            mma16816(accP[2 * np + 1], aP, b[np][2], b[np][3]);
            mma16816(accT[2 * np],     aT, b[np][0], b[np][1]);
            mma16816(accT[2 * np + 1], aT, b[np][2], b[np][3]);
        }
    }
    __syncthreads();                  // layer-2 act reads done

    epilogue(accP, accT, sBias + 192, smem, mh, n0, lane);
    __syncthreads();

    // ---------------- layer 3 (N=16), K split across warps ----------------
    {
        const int rowsel = (w >> 3) & 1;       // 0 = primal, 1 = tangent
        const int mh2    = (w >> 2) & 1;       // 32-row half
        const int kq     = w & 3;              // K quarter (3 ksteps)
        const int mbase  = rowsel * 64 + mh2 * 32;

        float acc3[2][2][4];
#pragma unroll
        for (int i = 0; i < 2; i++)
#pragma unroll
            for (int j = 0; j < 2; j++)
#pragma unroll
                for (int q = 0; q < 4; q++) acc3[i][j][q] = 0.f;
#pragma unroll
        for (int j = 0; j < 3; j++) {
            const int kt = kq * 3 + j;
            uint32_t b[4], a0[4], a1[4];
            ldsm4(b,  bAddr(swW3, 0, kt, lane));
            ldsm4(a0, aAddr(swA, mbase,      kt, lane));
            ldsm4(a1, aAddr(swA, mbase + 16, kt, lane));
            mma16816(acc3[0][0], a0, b[0], b[1]);
            mma16816(acc3[0][1], a0, b[2], b[3]);
            mma16816(acc3[1][0], a1, b[0], b[1]);
            mma16816(acc3[1][1], a1, b[2], b[3]);
        }
        // partial sums -> sRed[(rowsel*4+kq)][64 rows][16]  (aliases dead W1)
        float* red = sRed + (rowsel * 4 + kq) * 1024;
        const int rbase = mh2 * 32 + (lane >> 2);
        const int cl = 2 * (lane & 3);
#pragma unroll
        for (int mt = 0; mt < 2; mt++)
#pragma unroll
            for (int nt = 0; nt < 2; nt++)
#pragma unroll
                for (int rh = 0; rh < 2; rh++) {
                    const int r = rbase + 16 * mt + 8 * rh;
                    const int c = 8 * nt + cl;
                    *(float2*)(red + r * 16 + c) =
                        make_float2(acc3[mt][nt][2 * rh], acc3[mt][nt][2 * rh + 1]);
                }
    }
    __syncthreads();

    // ---------------- reduce partials -> outputs ----------------
    for (int i = tid; i < SAMP * 16; i += THREADS) {
        const int s = i >> 4, c = i & 15;
        float v = sRed[s * 16 + c] + sRed[1024 + s * 16 + c]
                + sRed[2048 + s * 16 + c] + sRed[3072 + s * 16 + c];
        outF[(size_t)(row0 + s) * Dd + c] = v + __ldg(b3 + c);
    }
    {
        const int s = tid >> 3, g = tid & 7, c0 = 2 * g;
        const float* rt_ = sRed + 4096 + s * 16 + c0;
        float j0 = rt_[0] + rt_[1024] + rt_[2048] + rt_[3072];
        float j1 = rt_[1] + rt_[1025] + rt_[2049] + rt_[3073];
        float2 ev = *(const float2*)(eps + (size_t)(row0 + s) * Dd + c0);
        float dot = j0 * ev.x + j1 * ev.y;
        dot += __shfl_xor_sync(0xffffffffu, dot, 1);
        dot += __shfl_xor_sync(0xffffffffu, dot, 2);
        dot += __shfl_xor_sync(0xffffffffu, dot, 4);
        if (g == 0) outLogp[row0 + s] = -dot;
    }
}

// ---------------- launcher ----------------
extern "C" void kernel_launch(void* const* d_in, const int* in_sizes, int n_in,
                              void* d_out, int out_size)
{
    const float* t   = (const float*)d_in[0];
    const float* y   = (const float*)d_in[1];
    const float* h   = (const float*)d_in[3];
    const float* eps = (const float*)d_in[4];
    const float* W1  = (const float*)d_in[5];
    const float* b1  = (const float*)d_in[6];
    const float* W2  = (const float*)d_in[7];
    const float* b2  = (const float*)d_in[8];
    const float* W3  = (const float*)d_in[9];
    const float* b3  = (const float*)d_in[10];

    const int Bsz = in_sizes[1] / Dd;

    prep<<<(67776 + 255) / 256, 256>>>(W1, W2, W3, b1, t);

    cudaFuncSetAttribute(odefunc_mma4,
                         cudaFuncAttributeMaxDynamicSharedMemorySize, SM_TOT);
    odefunc_mma4<<<Bsz / SAMP, THREADS, SM_TOT>>>(
        y, h, eps, b2, b3, (float*)d_out, Bsz);
}

// round 7
// speedup vs baseline: 1.1304x; 1.1304x over previous
#include <cuda_runtime.h>
#include <cuda_fp16.h>
#include <cstdint>
#include <math.h>

// ---------------- constants ----------------
#define Dd      16
#define CTXd    128
#define SAMP    64
#define THREADS 512
#define STRB    400           // act row pitch (bytes): conflict-free for ldmatrix

// smem layout (bytes)
#define SM_A    0             // activation: 128 rows x 400 B (51200)
#define SM_BIAS 51200         // 384 fp32
#define SM_TOT  52736
// layer-3 partials (32KB) alias SM_A after a sync

// fragment-image block counts (one block = n16 x k16 = 128 uint32 = 512B)
#define W1BLK   (12*9)        // n-groups x ksteps (K=144)
#define W2BLK   (12*12)
#define W3BLK   12            // n-group 0 only, 12 ksteps

__device__ __align__(16) uint32_t g_w1f[W1BLK*128];
__device__ __align__(16) uint32_t g_w2f[W2BLK*128];
__device__ __align__(16) uint32_t g_w3f[W3BLK*128];
__device__ float g_b1p[192];

// ---------------- prep: weights -> mma-B fragment order ----------------
// For block (n16g, kt), lane l, reg r:
//   n = n16g*16 + (l>>2) + ((r>>1)&1)*8
//   k = kt*16  + 2*(l&3) + (r&1)*8
//   value = half2( W[k][n], W[k+1][n] )
__global__ void prep(const float* __restrict__ W1, const float* __restrict__ W2,
                     const float* __restrict__ W3, const float* __restrict__ b1,
                     const float* __restrict__ t)
{
    int idx = blockIdx.x * blockDim.x + threadIdx.x;
    const float* W; uint32_t* img; int ktn, N, i;
    if (idx < W1BLK*128)               { i = idx;              W = W1; img = g_w1f; ktn = 9;  N = 192; }
    else if (idx < (W1BLK+W2BLK)*128)  { i = idx - W1BLK*128;  W = W2; img = g_w2f; ktn = 12; N = 192; }
    else if (idx < (W1BLK+W2BLK+W3BLK)*128)
                                       { i = idx - (W1BLK+W2BLK)*128; W = W3; img = g_w3f; ktn = 12; N = 16; }
    else if (idx < (W1BLK+W2BLK+W3BLK)*128 + 192) {
        int n = idx - (W1BLK+W2BLK+W3BLK)*128;
        g_b1p[n] = b1[n] + t[0] * W1[144 * 192 + n];
        return;
    } else return;

    int blk = i >> 7, li = i & 127;
    int lane = li >> 2, r = li & 3;
    int n16g = blk / ktn, kt = blk - n16g * ktn;
    int n = n16g * 16 + (lane >> 2) + ((r >> 1) & 1) * 8;
    int k = kt * 16 + 2 * (lane & 3) + (r & 1) * 8;
    __half2 v = __floats2half2_rn(W[(size_t)k * N + n], W[(size_t)(k + 1) * N + n]);
    img[i] = *(uint32_t*)&v;
}

// ---------------- PTX helpers ----------------
__device__ __forceinline__ uint32_t smem_u32(const void* p) {
    uint32_t a;
    asm("{ .reg .u64 t; cvta.to.shared.u64 t, %1; cvt.u32.u64 %0, t; }" : "=r"(a) : "l"(p));
    return a;
}
__device__ __forceinline__ void ldsm4(uint32_t (&r)[4], uint32_t addr) {
    asm volatile("ldmatrix.sync.aligned.m8n8.x4.shared.b16 {%0,%1,%2,%3}, [%4];"
                 : "=r"(r[0]), "=r"(r[1]), "=r"(r[2]), "=r"(r[3]) : "r"(addr));
}
__device__ __forceinline__ void mma16816(float (&d)[4], const uint32_t (&a)[4],
                                         uint32_t b0, uint32_t b1)
{
    asm volatile("mma.sync.aligned.m16n8k16.row.col.f32.f16.f16.f32 "
                 "{%0,%1,%2,%3}, {%4,%5,%6,%7}, {%8,%9}, {%0,%1,%2,%3};"
                 : "+f"(d[0]), "+f"(d[1]), "+f"(d[2]), "+f"(d[3])
                 : "r"(a[0]), "r"(a[1]), "r"(a[2]), "r"(a[3]), "r"(b0), "r"(b1));
}
__device__ __forceinline__ void ldgB(uint32_t (&b)[4], const uint32_t* __restrict__ img,
                                     int blk, int lane)
{
    const uint4 v = __ldg((const uint4*)(img + blk * 128 + lane * 4));
    b[0] = v.x; b[1] = v.y; b[2] = v.z; b[3] = v.w;
}

// A-fragment ldmatrix address (linear stride-400, conflict-free)
__device__ __forceinline__ uint32_t aAddr(uint32_t base, int m0, int kt, int lane) {
    int row = m0 + (lane & 7) + ((lane >> 3) & 1) * 8;
    return base + row * STRB + kt * 32 + ((lane >> 4) & 1) * 16;
}
__device__ __forceinline__ void stH2(char* sm, int row, int c0, float v0, float v1) {
    *(__half2*)(sm + SM_A + row * STRB + c0 * 2) = __floats2half2_rn(v0, v1);
}
__device__ __forceinline__ uint32_t packh2(float2 v) {
    __half2 hh = __floats2half2_rn(v.x, v.y);
    return *(uint32_t*)&hh;
}

__device__ __forceinline__ void gelu2(float a0, float a1, float& g0, float& g1,
                                      float& p0, float& p1)
{
    float c0 = 0.5f * (1.0f + erff(a0 * 0.70710678118654752f));
    float c1 = 0.5f * (1.0f + erff(a1 * 0.70710678118654752f));
    float q0 = 0.3989422804014327f * __expf(-0.5f * a0 * a0);
    float q1 = 0.3989422804014327f * __expf(-0.5f * a1 * a1);
    g0 = a0 * c0;  g1 = a1 * c1;
    p0 = c0 + a0 * q0;  p1 = c1 + a1 * q1;
}

__device__ __forceinline__ void epilogue(float (&accP)[6][4], float (&accT)[6][4],
                                         const float* bias, char* smem,
                                         int mh, int n0, int lane)
{
    const int r0 = mh * 16 + (lane >> 2);
    const int cl = 2 * (lane & 3);
#pragma unroll
    for (int nt = 0; nt < 6; nt++) {
        const int c0 = n0 + 8 * nt + cl;
        const float bb0 = bias[c0], bb1 = bias[c0 + 1];
#pragma unroll
        for (int rh = 0; rh < 2; rh++) {
            const int s = r0 + 8 * rh;
            float a0 = accP[nt][2 * rh]     + bb0;
            float a1 = accP[nt][2 * rh + 1] + bb1;
            float g0, g1, p0, p1;
            gelu2(a0, a1, g0, g1, p0, p1);
            stH2(smem, s, c0, g0, g1);
            stH2(smem, 64 + s, c0, accT[nt][2 * rh] * p0, accT[nt][2 * rh + 1] * p1);
        }
    }
}

// ---------------- main kernel ----------------
__global__ void __launch_bounds__(THREADS, 1)
odefunc_mma5(const float* __restrict__ y,
             const float* __restrict__ h,
             const float* __restrict__ eps,
             const float* __restrict__ b2,
             const float* __restrict__ b3,
             float* __restrict__ out, int Bsz)
{
    extern __shared__ __align__(16) char smem[];
    const uint32_t swA = smem_u32(smem) + SM_A;
    float* sBias = (float*)(smem + SM_BIAS);
    float* sRed  = (float*)(smem + SM_A);      // aliases act (after sync)

    const int tid  = threadIdx.x;
    const int lane = tid & 31;
    const int w    = tid >> 5;          // 0..15
    const int nq   = w & 3;             // n-quarter (48 cols)
    const int mh   = w >> 2;            // m-group (16 rows)
    const int n0   = nq * 48;

    const int row0 = blockIdx.x * SAMP;
    float* outF    = out;
    float* outLogp = out + (size_t)Bsz * Dd;
    float* outDh   = out + (size_t)Bsz * (Dd + 1);

    // ---- prologue: biases, zero dh, stage primal inputs ----
    if (tid < 192) sBias[tid] = g_b1p[tid];
    else if (tid >= 256 && tid < 448) sBias[tid - 64] = __ldg(b2 + (tid - 256));
    {
        float4* dhp = (float4*)(outDh + (size_t)row0 * CTXd);
        const float4 z4 = make_float4(0.f, 0.f, 0.f, 0.f);
        for (int i = tid; i < SAMP * CTXd / 4; i += THREADS) dhp[i] = z4;
    }
    {   // primal rows 0..63: [y(16) | h(128)] = K 144
        const int s = tid >> 3, kb = tid & 7;
#pragma unroll
        for (int j = 0; j < 9; j++) {
            const int k = 2 * (kb + 8 * j);
            float2 v;
            if (k < 16) v = *(const float2*)(y + (size_t)(row0 + s) * Dd + k);
            else        v = *(const float2*)(h + (size_t)(row0 + s) * CTXd + (k - 16));
            stH2(smem, s, k, v.x, v.y);
        }
    }
    __syncthreads();

    // ---------------- layer 1 ----------------
    float accP[6][4], accT[6][4];
#pragma unroll
    for (int j = 0; j < 6; j++)
#pragma unroll
        for (int q = 0; q < 4; q++) { accP[j][q] = 0.f; accT[j][q] = 0.f; }

    {   // kt = 0: primal (y cols) + tangent (eps fragment straight from gmem)
        uint32_t aT[4];
        {
            const float* eb = eps + (size_t)(row0 + mh * 16) * Dd;
            const int rr = lane >> 2, cc = 2 * (lane & 3);
            aT[0] = packh2(*(const float2*)(eb + rr * Dd + cc));
            aT[1] = packh2(*(const float2*)(eb + (rr + 8) * Dd + cc));
            aT[2] = packh2(*(const float2*)(eb + rr * Dd + cc + 8));
            aT[3] = packh2(*(const float2*)(eb + (rr + 8) * Dd + cc + 8));
        }
        uint32_t aP[4];
        ldsm4(aP, aAddr(swA, mh * 16, 0, lane));
#pragma unroll
        for (int np = 0; np < 3; np++) {
            uint32_t b[4];
            ldgB(b, g_w1f, (nq * 3 + np) * 9 + 0, lane);
            mma16816(accP[2 * np],     aP, b[0], b[1]);
            mma16816(accP[2 * np + 1], aP, b[2], b[3]);
            mma16816(accT[2 * np],     aT, b[0], b[1]);
            mma16816(accT[2 * np + 1], aT, b[2], b[3]);
        }
    }
#pragma unroll
    for (int kt = 1; kt < 9; kt++) {
        uint32_t aP[4];
        ldsm4(aP, aAddr(swA, mh * 16, kt, lane));
#pragma unroll
        for (int np = 0; np < 3; np++) {
            uint32_t b[4];
            ldgB(b, g_w1f, (nq * 3 + np) * 9 + kt, lane);
            mma16816(accP[2 * np],     aP, b[0], b[1]);
            mma16816(accP[2 * np + 1], aP, b[2], b[3]);
        }
    }
    __syncthreads();                  // layer-1 act reads done

    epilogue(accP, accT, sBias, smem, mh, n0, lane);
    __syncthreads();

    // ---------------- layer 2 ----------------
#pragma unroll
    for (int j = 0; j < 6; j++)
#pragma unroll
        for (int q = 0; q < 4; q++) { accP[j][q] = 0.f; accT[j][q] = 0.f; }
#pragma unroll
    for (int kt = 0; kt < 12; kt++) {
        uint32_t aP[4], aT[4];
        ldsm4(aP, aAddr(swA, mh * 16,      kt, lane));
        ldsm4(aT, aAddr(swA, 64 + mh * 16, kt, lane));
#pragma unroll
        for (int np = 0; np < 3; np++) {
            uint32_t b[4];
            ldgB(b, g_w2f, (nq * 3 + np) * 12 + kt, lane);
            mma16816(accP[2 * np],     aP, b[0], b[1]);
            mma16816(accP[2 * np + 1], aP, b[2], b[3]);
            mma16816(accT[2 * np],     aT, b[0], b[1]);
            mma16816(accT[2 * np + 1], aT, b[2], b[3]);
        }
    }
    __syncthreads();                  // layer-2 act reads done

    epilogue(accP, accT, sBias + 192, smem, mh, n0, lane);
    __syncthreads();

    // ---------------- layer 3 (N=16), K split across warps ----------------
    float acc3[2][2][4];
    {
        const int rowsel = (w >> 3) & 1;       // 0 = primal, 1 = tangent
        const int mh2    = (w >> 2) & 1;       // 32-row half
        const int kq     = w & 3;              // K quarter (3 ksteps)
        const int mbase  = rowsel * 64 + mh2 * 32;
#pragma unroll
        for (int i = 0; i < 2; i++)
#pragma unroll
            for (int j = 0; j < 2; j++)
#pragma unroll
                for (int q = 0; q < 4; q++) acc3[i][j][q] = 0.f;
#pragma unroll
        for (int j = 0; j < 3; j++) {
            const int kt = kq * 3 + j;
            uint32_t b[4], a0[4], a1[4];
            ldgB(b, g_w3f, kt, lane);
            ldsm4(a0, aAddr(swA, mbase,      kt, lane));
            ldsm4(a1, aAddr(swA, mbase + 16, kt, lane));
            mma16816(acc3[0][0], a0, b[0], b[1]);
            mma16816(acc3[0][1], a0, b[2], b[3]);
            mma16816(acc3[1][0], a1, b[0], b[1]);
            mma16816(acc3[1][1], a1, b[2], b[3]);
        }
    }
    __syncthreads();                  // all act reads done before aliasing as sRed

    {   // partial sums -> sRed[(rowsel*4+kq)][64 rows][16]
        const int rowsel = (w >> 3) & 1;
        const int mh2    = (w >> 2) & 1;
        const int kq     = w & 3;
        float* red = sRed + (rowsel * 4 + kq) * 1024;
        const int rbase = mh2 * 32 + (lane >> 2);
        const int cl = 2 * (lane & 3);
#pragma unroll
        for (int mt = 0; mt < 2; mt++)
#pragma unroll
            for (int nt = 0; nt < 2; nt++)
#pragma unroll
                for (int rh = 0; rh < 2; rh++) {
                    const int r = rbase + 16 * mt + 8 * rh;
                    const int c = 8 * nt + cl;
                    *(float2*)(red + r * 16 + c) =
                        make_float2(acc3[mt][nt][2 * rh], acc3[mt][nt][2 * rh + 1]);
                }
    }
    __syncthreads();

    // ---------------- reduce partials -> outputs ----------------
    for (int i = tid; i < SAMP * 16; i += THREADS) {
        const int s = i >> 4, c = i & 15;
        float v = sRed[s * 16 + c] + sRed[1024 + s * 16 + c]
                + sRed[2048 + s * 16 + c] + sRed[3072 + s * 16 + c];
        outF[(size_t)(row0 + s) * Dd + c] = v + __ldg(b3 + c);
    }
    {
        const int s = tid >> 3, g = tid & 7, c0 = 2 * g;
        const float* rt_ = sRed + 4096 + s * 16 + c0;
        float j0 = rt_[0] + rt_[1024] + rt_[2048] + rt_[3072];
        float j1 = rt_[1] + rt_[1025] + rt_[2049] + rt_[3073];
        float2 ev = *(const float2*)(eps + (size_t)(row0 + s) * Dd + c0);
        float dot = j0 * ev.x + j1 * ev.y;
        dot += __shfl_xor_sync(0xffffffffu, dot, 1);
        dot += __shfl_xor_sync(0xffffffffu, dot, 2);
        dot += __shfl_xor_sync(0xffffffffu, dot, 4);
        if (g == 0) outLogp[row0 + s] = -dot;
    }
}

// ---------------- launcher ----------------
extern "C" void kernel_launch(void* const* d_in, const int* in_sizes, int n_in,
                              void* d_out, int out_size)
{
    const float* t   = (const float*)d_in[0];
    const float* y   = (const float*)d_in[1];
    const float* h   = (const float*)d_in[3];
    const float* eps = (const float*)d_in[4];
    const float* W1  = (const float*)d_in[5];
    const float* b1  = (const float*)d_in[6];
    const float* W2  = (const float*)d_in[7];
    const float* b2  = (const float*)d_in[8];
    const float* W3  = (const float*)d_in[9];
    const float* b3  = (const float*)d_in[10];

    const int Bsz = in_sizes[1] / Dd;

    const int prepN = (W1BLK + W2BLK + W3BLK) * 128 + 192;
    prep<<<(prepN + 255) / 256, 256>>>(W1, W2, W3, b1, t);

    cudaFuncSetAttribute(odefunc_mma5,
                         cudaFuncAttributeMaxDynamicSharedMemorySize, SM_TOT);
    odefunc_mma5<<<Bsz / SAMP, THREADS, SM_TOT>>>(
        y, h, eps, b2, b3, (float*)d_out, Bsz);
}

// round 8
// speedup vs baseline: 1.1700x; 1.0350x over previous
#include <cuda_runtime.h>
#include <cuda_fp16.h>
#include <cstdint>
#include <math.h>

// ---------------- constants ----------------
#define Dd      16
#define CTXd    128
#define SAMP    64            // 2 groups x 32 samples
#define THREADS 512
#define STRB    400           // act row pitch (bytes)

// smem: two act buffers (64 rows x 400B each), group g at g*25600
#define SM_TOT  51200

// fragment-image block counts (one block = n16 x k16 = 128 uint32 = 512B)
#define W1BLK   (12*9)
#define W2BLK   (12*12)
#define W3BLK   12

__device__ __align__(16) uint32_t g_w1f[W1BLK*128];
__device__ __align__(16) uint32_t g_w2f[W2BLK*128];
__device__ __align__(16) uint32_t g_w3f[W3BLK*128];
__device__ float g_b1p[192];

// ---------------- prep: weights -> mma-B fragment order ----------------
__global__ void prep(const float* __restrict__ W1, const float* __restrict__ W2,
                     const float* __restrict__ W3, const float* __restrict__ b1,
                     const float* __restrict__ t)
{
    int idx = blockIdx.x * blockDim.x + threadIdx.x;
    const float* W; uint32_t* img; int ktn, N, i;
    if (idx < W1BLK*128)               { i = idx;              W = W1; img = g_w1f; ktn = 9;  N = 192; }
    else if (idx < (W1BLK+W2BLK)*128)  { i = idx - W1BLK*128;  W = W2; img = g_w2f; ktn = 12; N = 192; }
    else if (idx < (W1BLK+W2BLK+W3BLK)*128)
                                       { i = idx - (W1BLK+W2BLK)*128; W = W3; img = g_w3f; ktn = 12; N = 16; }
    else if (idx < (W1BLK+W2BLK+W3BLK)*128 + 192) {
        int n = idx - (W1BLK+W2BLK+W3BLK)*128;
        g_b1p[n] = b1[n] + t[0] * W1[144 * 192 + n];
        return;
    } else return;

    int blk = i >> 7, li = i & 127;
    int lane = li >> 2, r = li & 3;
    int n16g = blk / ktn, kt = blk - n16g * ktn;
    int n = n16g * 16 + (lane >> 2) + ((r >> 1) & 1) * 8;
    int k = kt * 16 + 2 * (lane & 3) + (r & 1) * 8;
    __half2 v = __floats2half2_rn(W[(size_t)k * N + n], W[(size_t)(k + 1) * N + n]);
    img[i] = *(uint32_t*)&v;
}

// ---------------- PTX helpers ----------------
__device__ __forceinline__ uint32_t smem_u32(const void* p) {
    uint32_t a;
    asm("{ .reg .u64 t; cvta.to.shared.u64 t, %1; cvt.u32.u64 %0, t; }" : "=r"(a) : "l"(p));
    return a;
}
__device__ __forceinline__ void barg(int id) {
    asm volatile("bar.sync %0, %1;" :: "r"(id), "r"(256) : "memory");
}
__device__ __forceinline__ void ldsm4(uint32_t (&r)[4], uint32_t addr) {
    asm volatile("ldmatrix.sync.aligned.m8n8.x4.shared.b16 {%0,%1,%2,%3}, [%4];"
                 : "=r"(r[0]), "=r"(r[1]), "=r"(r[2]), "=r"(r[3]) : "r"(addr));
}
__device__ __forceinline__ void mma16816(float (&d)[4], const uint32_t (&a)[4],
                                         uint32_t b0, uint32_t b1)
{
    asm volatile("mma.sync.aligned.m16n8k16.row.col.f32.f16.f16.f32 "
                 "{%0,%1,%2,%3}, {%4,%5,%6,%7}, {%8,%9}, {%0,%1,%2,%3};"
                 : "+f"(d[0]), "+f"(d[1]), "+f"(d[2]), "+f"(d[3])
                 : "r"(a[0]), "r"(a[1]), "r"(a[2]), "r"(a[3]), "r"(b0), "r"(b1));
}
__device__ __forceinline__ void ldgB(uint32_t (&b)[4], const uint32_t* __restrict__ img,
                                     int blk, int lane)
{
    const uint4 v = __ldg((const uint4*)(img + blk * 128 + lane * 4));
    b[0] = v.x; b[1] = v.y; b[2] = v.z; b[3] = v.w;
}
__device__ __forceinline__ uint32_t aAddr(uint32_t base, int m0, int kt, int lane) {
    int row = m0 + (lane & 7) + ((lane >> 3) & 1) * 8;
    return base + row * STRB + kt * 32 + ((lane >> 4) & 1) * 16;
}
__device__ __forceinline__ void stH2(char* sm, int row, int c0, float v0, float v1) {
    *(__half2*)(sm + row * STRB + c0 * 2) = __floats2half2_rn(v0, v1);
}
__device__ __forceinline__ uint32_t packh2(float2 v) {
    __half2 hh = __floats2half2_rn(v.x, v.y);
    return *(uint32_t*)&hh;
}
__device__ __forceinline__ void gelu2(float a0, float a1, float& g0, float& g1,
                                      float& p0, float& p1)
{
    float c0 = 0.5f * (1.0f + erff(a0 * 0.70710678118654752f));
    float c1 = 0.5f * (1.0f + erff(a1 * 0.70710678118654752f));
    float q0 = 0.3989422804014327f * __expf(-0.5f * a0 * a0);
    float q1 = 0.3989422804014327f * __expf(-0.5f * a1 * a1);
    g0 = a0 * c0;  g1 = a1 * c1;
    p0 = c0 + a0 * q0;  p1 = c1 + a1 * q1;
}

// bias (from gmem) + gelu on primal frag, gelu'(a)*u on tangent frag -> smem act
__device__ __forceinline__ void epilogue(float (&accP)[6][4], float (&accT)[6][4],
                                         const float* __restrict__ bias, char* sAct,
                                         int mh, int n0, int lane)
{
    const int r0 = mh * 16 + (lane >> 2);
    const int cl = 2 * (lane & 3);
#pragma unroll
    for (int nt = 0; nt < 6; nt++) {
        const int c0 = n0 + 8 * nt + cl;
        const float2 bb = __ldg((const float2*)(bias + c0));
#pragma unroll
        for (int rh = 0; rh < 2; rh++) {
            const int s = r0 + 8 * rh;
            float a0 = accP[nt][2 * rh]     + bb.x;
            float a1 = accP[nt][2 * rh + 1] + bb.y;
            float g0, g1, p0, p1;
            gelu2(a0, a1, g0, g1, p0, p1);
            stH2(sAct, s, c0, g0, g1);
            stH2(sAct, 32 + s, c0, accT[nt][2 * rh] * p0, accT[nt][2 * rh + 1] * p1);
        }
    }
}

// ---------------- main kernel ----------------
__global__ void __launch_bounds__(THREADS, 1)
odefunc_mma6(const float* __restrict__ y,
             const float* __restrict__ h,
             const float* __restrict__ eps,
             const float* __restrict__ b2,
             const float* __restrict__ b3,
             float* __restrict__ out, int Bsz)
{
    extern __shared__ __align__(16) char smem[];

    const int tid  = threadIdx.x;
    const int lane = tid & 31;
    const int w    = tid >> 5;          // 0..15
    const int g    = w >> 3;            // sample group 0/1
    const int wg   = w & 7;             // warp within group
    const int nq   = wg & 3;            // n-quarter (48 cols)
    const int mh   = wg >> 2;           // m-half (16 rows) 0/1
    const int n0   = nq * 48;
    const int gtid = tid & 255;
    const int bid  = g + 1;             // named barrier id

    char* sAct = smem + g * 25600;                 // 64 rows x 400B for this group
    const uint32_t swA = smem_u32(sAct);
    float* sRed = (float*)sAct;                    // aliases act after final sync

    const int srow0 = blockIdx.x * SAMP + g * 32;  // group's global sample base
    float* outF    = out;
    float* outLogp = out + (size_t)Bsz * Dd;
    float* outDh   = out + (size_t)Bsz * (Dd + 1);

    // ---- prologue (per group): zero dh, stage primal inputs ----
    {
        float4* dhp = (float4*)(outDh + (size_t)srow0 * CTXd);
        const float4 z4 = make_float4(0.f, 0.f, 0.f, 0.f);
        for (int i = gtid; i < 32 * CTXd / 4; i += 256) dhp[i] = z4;
    }
    {   // primal rows 0..31: [y(16) | h(128)] = K 144
        const int s = gtid >> 3, kb = gtid & 7;
#pragma unroll
        for (int j = 0; j < 9; j++) {
            const int k = 2 * (kb + 8 * j);
            float2 v;
            if (k < 16) v = *(const float2*)(y + (size_t)(srow0 + s) * Dd + k);
            else        v = *(const float2*)(h + (size_t)(srow0 + s) * CTXd + (k - 16));
            stH2(sAct, s, k, v.x, v.y);
        }
    }
    barg(bid);

    // ---------------- layer 1 ----------------
    float accP[6][4], accT[6][4];
#pragma unroll
    for (int j = 0; j < 6; j++)
#pragma unroll
        for (int q = 0; q < 4; q++) { accP[j][q] = 0.f; accT[j][q] = 0.f; }

    {   // kt = 0: primal from smem, tangent (eps) fragment straight from gmem
        uint32_t aT[4];
        {
            const float* eb = eps + (size_t)(srow0 + mh * 16) * Dd;
            const int rr = lane >> 2, cc = 2 * (lane & 3);
            aT[0] = packh2(*(const float2*)(eb + rr * Dd + cc));
            aT[1] = packh2(*(const float2*)(eb + (rr + 8) * Dd + cc));
            aT[2] = packh2(*(const float2*)(eb + rr * Dd + cc + 8));
            aT[3] = packh2(*(const float2*)(eb + (rr + 8) * Dd + cc + 8));
        }
        uint32_t aP[4];
        ldsm4(aP, aAddr(swA, mh * 16, 0, lane));
#pragma unroll
        for (int np = 0; np < 3; np++) {
            uint32_t b[4];
            ldgB(b, g_w1f, (nq * 3 + np) * 9 + 0, lane);
            mma16816(accP[2 * np],     aP, b[0], b[1]);
            mma16816(accP[2 * np + 1], aP, b[2], b[3]);
            mma16816(accT[2 * np],     aT, b[0], b[1]);
            mma16816(accT[2 * np + 1], aT, b[2], b[3]);
        }
    }
#pragma unroll
    for (int kt = 1; kt < 9; kt++) {
        uint32_t aP[4];
        ldsm4(aP, aAddr(swA, mh * 16, kt, lane));
#pragma unroll
        for (int np = 0; np < 3; np++) {
            uint32_t b[4];
            ldgB(b, g_w1f, (nq * 3 + np) * 9 + kt, lane);
            mma16816(accP[2 * np],     aP, b[0], b[1]);
            mma16816(accP[2 * np + 1], aP, b[2], b[3]);
        }
    }
    barg(bid);                        // layer-1 act reads done

    epilogue(accP, accT, g_b1p, sAct, mh, n0, lane);
    barg(bid);

    // ---------------- layer 2 ----------------
#pragma unroll
    for (int j = 0; j < 6; j++)
#pragma unroll
        for (int q = 0; q < 4; q++) { accP[j][q] = 0.f; accT[j][q] = 0.f; }
#pragma unroll
    for (int kt = 0; kt < 12; kt++) {
        uint32_t aP[4], aT[4];
        ldsm4(aP, aAddr(swA, mh * 16,      kt, lane));
        ldsm4(aT, aAddr(swA, 32 + mh * 16, kt, lane));
#pragma unroll
        for (int np = 0; np < 3; np++) {
            uint32_t b[4];
            ldgB(b, g_w2f, (nq * 3 + np) * 12 + kt, lane);
            mma16816(accP[2 * np],     aP, b[0], b[1]);
            mma16816(accP[2 * np + 1], aP, b[2], b[3]);
            mma16816(accT[2 * np],     aT, b[0], b[1]);
            mma16816(accT[2 * np + 1], aT, b[2], b[3]);
        }
    }
    barg(bid);                        // layer-2 act reads done

    epilogue(accP, accT, b2, sAct, mh, n0, lane);
    barg(bid);

    // ---------------- layer 3 (N=16), K split across group warps ----------------
    float acc3[2][2][4];
    const int rowsel = wg >> 2;       // 0 = primal, 1 = tangent (32-row set)
    const int kq     = wg & 3;        // K quarter (3 ksteps)
    {
        const int mbase = rowsel * 32;
#pragma unroll
        for (int i = 0; i < 2; i++)
#pragma unroll
            for (int j = 0; j < 2; j++)
#pragma unroll
                for (int q = 0; q < 4; q++) acc3[i][j][q] = 0.f;
#pragma unroll
        for (int j = 0; j < 3; j++) {
            const int kt = kq * 3 + j;
            uint32_t b[4], a0[4], a1[4];
            ldgB(b, g_w3f, kt, lane);
            ldsm4(a0, aAddr(swA, mbase,      kt, lane));
            ldsm4(a1, aAddr(swA, mbase + 16, kt, lane));
            mma16816(acc3[0][0], a0, b[0], b[1]);
            mma16816(acc3[0][1], a0, b[2], b[3]);
            mma16816(acc3[1][0], a1, b[0], b[1]);
            mma16816(acc3[1][1], a1, b[2], b[3]);
        }
    }
    barg(bid);                        // all act reads done before aliasing as sRed

    {   // partials -> sRed[(rowsel*4+kq)][32 rows][16]
        float* red = sRed + (rowsel * 4 + kq) * 512;
        const int rbase = lane >> 2;
        const int cl = 2 * (lane & 3);
#pragma unroll
        for (int mt = 0; mt < 2; mt++)
#pragma unroll
            for (int nt = 0; nt < 2; nt++)
#pragma unroll
                for (int rh = 0; rh < 2; rh++) {
                    const int r = rbase + 16 * mt + 8 * rh;
                    const int c = 8 * nt + cl;
                    *(float2*)(red + r * 16 + c) =
                        make_float2(acc3[mt][nt][2 * rh], acc3[mt][nt][2 * rh + 1]);
                }
    }
    barg(bid);

    // ---------------- reduce partials -> outputs ----------------
    for (int i = gtid; i < 32 * 16; i += 256) {
        const int s = i >> 4, c = i & 15;
        float v = sRed[s * 16 + c] + sRed[512 + s * 16 + c]
                + sRed[1024 + s * 16 + c] + sRed[1536 + s * 16 + c];
        outF[(size_t)(srow0 + s) * Dd + c] = v + __ldg(b3 + c);
    }
    {
        const int s = gtid >> 3, g8 = gtid & 7, c0 = 2 * g8;
        const float* rt_ = sRed + 2048 + s * 16 + c0;
        float j0 = rt_[0] + rt_[512] + rt_[1024] + rt_[1536];
        float j1 = rt_[1] + rt_[513] + rt_[1025] + rt_[1537];
        float2 ev = *(const float2*)(eps + (size_t)(srow0 + s) * Dd + c0);
        float dot = j0 * ev.x + j1 * ev.y;
        dot += __shfl_xor_sync(0xffffffffu, dot, 1);
        dot += __shfl_xor_sync(0xffffffffu, dot, 2);
        dot += __shfl_xor_sync(0xffffffffu, dot, 4);
        if (g8 == 0) outLogp[srow0 + s] = -dot;
    }
}

// ---------------- launcher ----------------
extern "C" void kernel_launch(void* const* d_in, const int* in_sizes, int n_in,
                              void* d_out, int out_size)
{
    const float* t   = (const float*)d_in[0];
    const float* y   = (const float*)d_in[1];
    const float* h   = (const float*)d_in[3];
    const float* eps = (const float*)d_in[4];
    const float* W1  = (const float*)d_in[5];
    const float* b1  = (const float*)d_in[6];
    const float* W2  = (const float*)d_in[7];
    const float* b2  = (const float*)d_in[8];
    const float* W3  = (const float*)d_in[9];
    const float* b3  = (const float*)d_in[10];

    const int Bsz = in_sizes[1] / Dd;

    const int prepN = (W1BLK + W2BLK + W3BLK) * 128 + 192;
    prep<<<(prepN + 255) / 256, 256>>>(W1, W2, W3, b1, t);

    cudaFuncSetAttribute(odefunc_mma6,
                         cudaFuncAttributeMaxDynamicSharedMemorySize, SM_TOT);
    odefunc_mma6<<<Bsz / SAMP, THREADS, SM_TOT>>>(
        y, h, eps, b2, b3, (float*)d_out, Bsz);
}

// round 9
// speedup vs baseline: 1.2712x; 1.0864x over previous
#include <cuda_runtime.h>
#include <cuda_fp16.h>
#include <cstdint>
#include <math.h>

// ---------------- constants ----------------
#define Dd      16
#define CTXd    128
#define SAMP    64            // 2 groups x 32 samples
#define THREADS 512
#define STRB    400           // act row pitch (bytes)

// smem: two act buffers (64 rows x 400B each), group g at g*25600
#define SM_TOT  51200

// fragment-image block counts (one block = n16 x k16 = 128 uint32 = 512B)
#define W1BLK   (12*9)
#define W2BLK   (12*12)
#define W3BLK   12

__device__ __align__(16) uint32_t g_w1f[W1BLK*128];
__device__ __align__(16) uint32_t g_w2f[W2BLK*128];
__device__ __align__(16) uint32_t g_w3f[W3BLK*128];
__device__ float g_b1p[192];

// ---------------- prep: weights -> mma-B fragment order ----------------
__global__ void prep(const float* __restrict__ W1, const float* __restrict__ W2,
                     const float* __restrict__ W3, const float* __restrict__ b1,
                     const float* __restrict__ t)
{
    int idx = blockIdx.x * blockDim.x + threadIdx.x;
    const float* W; uint32_t* img; int ktn, N, i;
    if (idx < W1BLK*128)               { i = idx;              W = W1; img = g_w1f; ktn = 9;  N = 192; }
    else if (idx < (W1BLK+W2BLK)*128)  { i = idx - W1BLK*128;  W = W2; img = g_w2f; ktn = 12; N = 192; }
    else if (idx < (W1BLK+W2BLK+W3BLK)*128)
                                       { i = idx - (W1BLK+W2BLK)*128; W = W3; img = g_w3f; ktn = 12; N = 16; }
    else if (idx < (W1BLK+W2BLK+W3BLK)*128 + 192) {
        int n = idx - (W1BLK+W2BLK+W3BLK)*128;
        g_b1p[n] = b1[n] + t[0] * W1[144 * 192 + n];
        return;
    } else return;

    int blk = i >> 7, li = i & 127;
    int lane = li >> 2, r = li & 3;
    int n16g = blk / ktn, kt = blk - n16g * ktn;
    int n = n16g * 16 + (lane >> 2) + ((r >> 1) & 1) * 8;
    int k = kt * 16 + 2 * (lane & 3) + (r & 1) * 8;
    __half2 v = __floats2half2_rn(W[(size_t)k * N + n], W[(size_t)(k + 1) * N + n]);
    img[i] = *(uint32_t*)&v;
}

// ---------------- PTX helpers ----------------
__device__ __forceinline__ uint32_t smem_u32(const void* p) {
    uint32_t a;
    asm("{ .reg .u64 t; cvta.to.shared.u64 t, %1; cvt.u32.u64 %0, t; }" : "=r"(a) : "l"(p));
    return a;
}
__device__ __forceinline__ void barg(int id) {
    asm volatile("bar.sync %0, %1;" :: "r"(id), "r"(256) : "memory");
}
__device__ __forceinline__ void ldsm4(uint32_t (&r)[4], uint32_t addr) {
    asm volatile("ldmatrix.sync.aligned.m8n8.x4.shared.b16 {%0,%1,%2,%3}, [%4];"
                 : "=r"(r[0]), "=r"(r[1]), "=r"(r[2]), "=r"(r[3]) : "r"(addr));
}
__device__ __forceinline__ void mma16816(float (&d)[4], const uint32_t (&a)[4],
                                         uint32_t b0, uint32_t b1)
{
    asm volatile("mma.sync.aligned.m16n8k16.row.col.f32.f16.f16.f32 "
                 "{%0,%1,%2,%3}, {%4,%5,%6,%7}, {%8,%9}, {%0,%1,%2,%3};"
                 : "+f"(d[0]), "+f"(d[1]), "+f"(d[2]), "+f"(d[3])
                 : "r"(a[0]), "r"(a[1]), "r"(a[2]), "r"(a[3]), "r"(b0), "r"(b1));
}
__device__ __forceinline__ void ldgB(uint32_t (&b)[4], const uint32_t* __restrict__ img,
                                     int blk, int lane)
{
    const uint4 v = __ldg((const uint4*)(img + blk * 128 + lane * 4));
    b[0] = v.x; b[1] = v.y; b[2] = v.z; b[3] = v.w;
}
__device__ __forceinline__ uint32_t aAddr(uint32_t base, int m0, int kt, int lane) {
    int row = m0 + (lane & 7) + ((lane >> 3) & 1) * 8;
    return base + row * STRB + kt * 32 + ((lane >> 4) & 1) * 16;
}
__device__ __forceinline__ void stH2(char* sm, int row, int c0, float v0, float v1) {
    *(__half2*)(sm + row * STRB + c0 * 2) = __floats2half2_rn(v0, v1);
}
__device__ __forceinline__ uint32_t packh2(float2 v) {
    __half2 hh = __floats2half2_rn(v.x, v.y);
    return *(uint32_t*)&hh;
}
__device__ __forceinline__ float rcpa(float x) {
    float r; asm("rcp.approx.f32 %0, %1;" : "=f"(r) : "f"(x)); return r;
}

// Fast exact-GELU + derivative via A&S 7.1.26 (|err| <= 1.5e-7), reusing E=exp(-a^2/2).
// cdf = a>=0 ? 1 - q : q, with q = (0.5*poly(t))*E, t = 1/(1+0.3275911*|a|/sqrt2)
#define GA1  0.127414796f
#define GA2 -0.142248368f
#define GA3  0.71070687f
#define GA4 -0.72657601f
#define GA5  0.53070271f
__device__ __forceinline__ void gelu2(float a0, float a1, float& g0, float& g1,
                                      float& p0, float& p1)
{
    float e0 = __expf(-0.5f * a0 * a0);
    float e1 = __expf(-0.5f * a1 * a1);
    float x0 = fabsf(a0) * 0.70710678f;
    float x1 = fabsf(a1) * 0.70710678f;
    float t0 = rcpa(fmaf(0.3275911f, x0, 1.0f));
    float t1 = rcpa(fmaf(0.3275911f, x1, 1.0f));
    float s0 = t0 * fmaf(t0, fmaf(t0, fmaf(t0, fmaf(t0, GA5, GA4), GA3), GA2), GA1);
    float s1 = t1 * fmaf(t1, fmaf(t1, fmaf(t1, fmaf(t1, GA5, GA4), GA3), GA2), GA1);
    float q0 = s0 * e0;
    float q1 = s1 * e1;
    float c0 = (a0 >= 0.f) ? (1.0f - q0) : q0;
    float c1 = (a1 >= 0.f) ? (1.0f - q1) : q1;
    g0 = a0 * c0;  g1 = a1 * c1;
    p0 = fmaf(a0, 0.3989423f * e0, c0);
    p1 = fmaf(a1, 0.3989423f * e1, c1);
}

// bias (from gmem) + gelu on primal frag, gelu'(a)*u on tangent frag -> smem act
__device__ __forceinline__ void epilogue(float (&accP)[6][4], float (&accT)[6][4],
                                         const float* __restrict__ bias, char* sAct,
                                         int mh, int n0, int lane)
{
    const int r0 = mh * 16 + (lane >> 2);
    const int cl = 2 * (lane & 3);
#pragma unroll
    for (int nt = 0; nt < 6; nt++) {
        const int c0 = n0 + 8 * nt + cl;
        const float2 bb = __ldg((const float2*)(bias + c0));
#pragma unroll
        for (int rh = 0; rh < 2; rh++) {
            const int s = r0 + 8 * rh;
            float a0 = accP[nt][2 * rh]     + bb.x;
            float a1 = accP[nt][2 * rh + 1] + bb.y;
            float g0, g1, p0, p1;
            gelu2(a0, a1, g0, g1, p0, p1);
            stH2(sAct, s, c0, g0, g1);
            stH2(sAct, 32 + s, c0, accT[nt][2 * rh] * p0, accT[nt][2 * rh + 1] * p1);
        }
    }
}

// ---------------- main kernel ----------------
__global__ void __launch_bounds__(THREADS, 1)
odefunc_mma7(const float* __restrict__ y,
             const float* __restrict__ h,
             const float* __restrict__ eps,
             const float* __restrict__ b2,
             const float* __restrict__ b3,
             float* __restrict__ out, int Bsz)
{
    extern __shared__ __align__(16) char smem[];

    const int tid  = threadIdx.x;
    const int lane = tid & 31;
    const int w    = tid >> 5;          // 0..15
    const int g    = w >> 3;            // sample group 0/1
    const int wg   = w & 7;             // warp within group
    const int nq   = wg & 3;            // n-quarter (48 cols)
    const int mh   = wg >> 2;           // m-half (16 rows) 0/1
    const int n0   = nq * 48;
    const int gtid = tid & 255;
    const int bid  = g + 1;             // named barrier id

    char* sAct = smem + g * 25600;
    const uint32_t swA = smem_u32(sAct);
    float* sRed = (float*)sAct;

    const int srow0 = blockIdx.x * SAMP + g * 32;
    float* outF    = out;
    float* outLogp = out + (size_t)Bsz * Dd;
    float* outDh   = out + (size_t)Bsz * (Dd + 1);

    // ---- prologue (per group): zero dh, stage primal inputs ----
    {
        float4* dhp = (float4*)(outDh + (size_t)srow0 * CTXd);
        const float4 z4 = make_float4(0.f, 0.f, 0.f, 0.f);
        for (int i = gtid; i < 32 * CTXd / 4; i += 256) dhp[i] = z4;
    }
    {   // primal rows 0..31: [y(16) | h(128)] = K 144, branch-free split
        const int s = gtid >> 3, kb = gtid & 7;
        {
            const int k = 2 * kb;                       // 0..14: from y
            float2 v = *(const float2*)(y + (size_t)(srow0 + s) * Dd + k);
            stH2(sAct, s, k, v.x, v.y);
        }
#pragma unroll
        for (int j = 1; j < 9; j++) {                    // 16..143: from h
            const int k = 2 * (kb + 8 * j);
            float2 v = *(const float2*)(h + (size_t)(srow0 + s) * CTXd + (k - 16));
            stH2(sAct, s, k, v.x, v.y);
        }
    }
    barg(bid);

    // ---------------- layer 1 ----------------
    float accP[6][4], accT[6][4];
#pragma unroll
    for (int j = 0; j < 6; j++)
#pragma unroll
        for (int q = 0; q < 4; q++) { accP[j][q] = 0.f; accT[j][q] = 0.f; }

    {   // kt = 0: primal from smem, tangent (eps) fragment straight from gmem
        uint32_t aT[4];
        {
            const float* eb = eps + (size_t)(srow0 + mh * 16) * Dd;
            const int rr = lane >> 2, cc = 2 * (lane & 3);
            aT[0] = packh2(*(const float2*)(eb + rr * Dd + cc));
            aT[1] = packh2(*(const float2*)(eb + (rr + 8) * Dd + cc));
            aT[2] = packh2(*(const float2*)(eb + rr * Dd + cc + 8));
            aT[3] = packh2(*(const float2*)(eb + (rr + 8) * Dd + cc + 8));
        }
        uint32_t aP[4];
        ldsm4(aP, aAddr(swA, mh * 16, 0, lane));
#pragma unroll
        for (int np = 0; np < 3; np++) {
            uint32_t b[4];
            ldgB(b, g_w1f, (nq * 3 + np) * 9 + 0, lane);
            mma16816(accP[2 * np],     aP, b[0], b[1]);
            mma16816(accP[2 * np + 1], aP, b[2], b[3]);
            mma16816(accT[2 * np],     aT, b[0], b[1]);
            mma16816(accT[2 * np + 1], aT, b[2], b[3]);
        }
    }
#pragma unroll
    for (int kt = 1; kt < 9; kt++) {
        uint32_t aP[4];
        ldsm4(aP, aAddr(swA, mh * 16, kt, lane));
#pragma unroll
        for (int np = 0; np < 3; np++) {
            uint32_t b[4];
            ldgB(b, g_w1f, (nq * 3 + np) * 9 + kt, lane);
            mma16816(accP[2 * np],     aP, b[0], b[1]);
            mma16816(accP[2 * np + 1], aP, b[2], b[3]);
        }
    }
    barg(bid);                        // layer-1 act reads done

    epilogue(accP, accT, g_b1p, sAct, mh, n0, lane);
    barg(bid);

    // ---------------- layer 2 ----------------
#pragma unroll
    for (int j = 0; j < 6; j++)
#pragma unroll
        for (int q = 0; q < 4; q++) { accP[j][q] = 0.f; accT[j][q] = 0.f; }
#pragma unroll
    for (int kt = 0; kt < 12; kt++) {
        uint32_t aP[4], aT[4];
        ldsm4(aP, aAddr(swA, mh * 16,      kt, lane));
        ldsm4(aT, aAddr(swA, 32 + mh * 16, kt, lane));
#pragma unroll
        for (int np = 0; np < 3; np++) {
            uint32_t b[4];
            ldgB(b, g_w2f, (nq * 3 + np) * 12 + kt, lane);
            mma16816(accP[2 * np],     aP, b[0], b[1]);
            mma16816(accP[2 * np + 1], aP, b[2], b[3]);
            mma16816(accT[2 * np],     aT, b[0], b[1]);
            mma16816(accT[2 * np + 1], aT, b[2], b[3]);
        }
    }
    barg(bid);                        // layer-2 act reads done

    epilogue(accP, accT, b2, sAct, mh, n0, lane);
    barg(bid);

    // ---------------- layer 3 (N=16), K split across group warps ----------------
    float acc3[2][2][4];
    const int rowsel = wg >> 2;
    const int kq     = wg & 3;
    {
        const int mbase = rowsel * 32;
#pragma unroll
        for (int i = 0; i < 2; i++)
#pragma unroll
            for (int j = 0; j < 2; j++)
#pragma unroll
                for (int q = 0; q < 4; q++) acc3[i][j][q] = 0.f;
#pragma unroll
        for (int j = 0; j < 3; j++) {
            const int kt = kq * 3 + j;
            uint32_t b[4], a0[4], a1[4];
            ldgB(b, g_w3f, kt, lane);
            ldsm4(a0, aAddr(swA, mbase,      kt, lane));
            ldsm4(a1, aAddr(swA, mbase + 16, kt, lane));
            mma16816(acc3[0][0], a0, b[0], b[1]);
            mma16816(acc3[0][1], a0, b[2], b[3]);
            mma16816(acc3[1][0], a1, b[0], b[1]);
            mma16816(acc3[1][1], a1, b[2], b[3]);
        }
    }
    barg(bid);                        // all act reads done before aliasing as sRed

    {   // partials -> sRed[(rowsel*4+kq)][32 rows][16]
        float* red = sRed + (rowsel * 4 + kq) * 512;
        const int rbase = lane >> 2;
        const int cl = 2 * (lane & 3);
#pragma unroll
        for (int mt = 0; mt < 2; mt++)
#pragma unroll
            for (int nt = 0; nt < 2; nt++)
#pragma unroll
                for (int rh = 0; rh < 2; rh++) {
                    const int r = rbase + 16 * mt + 8 * rh;
                    const int c = 8 * nt + cl;
                    *(float2*)(red + r * 16 + c) =
                        make_float2(acc3[mt][nt][2 * rh], acc3[mt][nt][2 * rh + 1]);
                }
    }
    barg(bid);

    // ---------------- reduce partials -> outputs ----------------
    for (int i = gtid; i < 32 * 16; i += 256) {
        const int s = i >> 4, c = i & 15;
        float v = sRed[s * 16 + c] + sRed[512 + s * 16 + c]
                + sRed[1024 + s * 16 + c] + sRed[1536 + s * 16 + c];
        outF[(size_t)(srow0 + s) * Dd + c] = v + __ldg(b3 + c);
    }
    {
        const int s = gtid >> 3, g8 = gtid & 7, c0 = 2 * g8;
        const float* rt_ = sRed + 2048 + s * 16 + c0;
        float j0 = rt_[0] + rt_[512] + rt_[1024] + rt_[1536];
        float j1 = rt_[1] + rt_[513] + rt_[1025] + rt_[1537];
        float2 ev = *(const float2*)(eps + (size_t)(srow0 + s) * Dd + c0);
        float dot = j0 * ev.x + j1 * ev.y;
        dot += __shfl_xor_sync(0xffffffffu, dot, 1);
        dot += __shfl_xor_sync(0xffffffffu, dot, 2);
        dot += __shfl_xor_sync(0xffffffffu, dot, 4);
        if (g8 == 0) outLogp[srow0 + s] = -dot;
    }
}

// ---------------- launcher ----------------
extern "C" void kernel_launch(void* const* d_in, const int* in_sizes, int n_in,
                              void* d_out, int out_size)
{
    const float* t   = (const float*)d_in[0];
    const float* y   = (const float*)d_in[1];
    const float* h   = (const float*)d_in[3];
    const float* eps = (const float*)d_in[4];
    const float* W1  = (const float*)d_in[5];
    const float* b1  = (const float*)d_in[6];
    const float* W2  = (const float*)d_in[7];
    const float* b2  = (const float*)d_in[8];
    const float* W3  = (const float*)d_in[9];
    const float* b3  = (const float*)d_in[10];

    const int Bsz = in_sizes[1] / Dd;

    const int prepN = (W1BLK + W2BLK + W3BLK) * 128 + 192;
    prep<<<(prepN + 255) / 256, 256>>>(W1, W2, W3, b1, t);

    cudaFuncSetAttribute(odefunc_mma7,
                         cudaFuncAttributeMaxDynamicSharedMemorySize, SM_TOT);
    odefunc_mma7<<<Bsz / SAMP, THREADS, SM_TOT>>>(
        y, h, eps, b2, b3, (float*)d_out, Bsz);
}